// round 17
// baseline (speedup 1.0000x reference)
#include <cuda_runtime.h>
#include <cuda_fp16.h>

// 24-qubit state-vector sim, 8 two-qubit gates, step s -> qubits (s, s+7).
// R17 = R15 tile structures fused into ONE persistent kernel with chunk-level
// dependency tracking (overlaps pass0 and pass1):
//   work items 0..8191   = pass0 tiles (gates 0..4, fp32 in -> fp16 mid)
//   work items 8192..16383 = pass1 tiles (gates 5..7, fp16 mid -> fp32 out)
// chunk = amp bits 15..23 (512 chunks); pass1 tile waits g_done[chunk]==16.
// Claim-one-complete-one work loop => deadlock-free at any residency.
// Items handed out by a global atomic; math per item is schedule-independent
// => deterministic output. Reset kernel zeroes counters each launch.

#define NSTATE (1u << 24)
typedef unsigned long long u64;

static __device__ __align__(16) unsigned g_mid[1u << 24];   // half2 per amp, 64MB
static __device__ int g_next;
static __device__ int g_done[512];

__device__ __forceinline__ u64 pk2(float lo, float hi) {
    u64 r; asm("mov.b64 %0, {%1, %2};" : "=l"(r) : "f"(lo), "f"(hi)); return r;
}
__device__ __forceinline__ void upk2(u64 v, float& lo, float& hi) {
    asm("mov.b64 {%0, %1}, %2;" : "=f"(lo), "=f"(hi) : "l"(v));
}
__device__ __forceinline__ u64 ffma2(u64 a, u64 b, u64 c) {
    u64 d; asm("fma.rn.f32x2 %0, %1, %2, %3;" : "=l"(d) : "l"(a), "l"(b), "l"(c)); return d;
}
__device__ __forceinline__ u64 fmul2(u64 a, u64 b) {
    u64 d; asm("mul.rn.f32x2 %0, %1, %2;" : "=l"(d) : "l"(a), "l"(b)); return d;
}
__device__ __forceinline__ u64 fadd2(u64 a, u64 b) {
    u64 d; asm("add.rn.f32x2 %0, %1, %2;" : "=l"(d) : "l"(a), "l"(b)); return d;
}
__device__ __forceinline__ float negf(float v) {
    return __int_as_float(__float_as_int(v) ^ 0x80000000u);
}
__device__ __forceinline__ unsigned SWZ(unsigned x) {
    return x ^ (((x >> 4) & 1u) * 5u) ^ (((x >> 5) & 1u) * 10u)
             ^ (((x >> 6) & 1u) * 1u);
}

__device__ __forceinline__ u64 mkpol_evict_first() {
    u64 p; asm("createpolicy.fractional.L2::evict_first.b64 %0, 1.0;" : "=l"(p));
    return p;
}
__device__ __forceinline__ u64 mkpol_evict_last() {
    u64 p; asm("createpolicy.fractional.L2::evict_last.b64 %0, 1.0;" : "=l"(p));
    return p;
}
__device__ __forceinline__ float4 ldg_stream(const float* p, u64 pol) {
    float4 v;
    asm volatile("ld.global.nc.L2::cache_hint.v4.f32 {%0,%1,%2,%3}, [%4], %5;"
                 : "=f"(v.x), "=f"(v.y), "=f"(v.z), "=f"(v.w) : "l"(p), "l"(pol));
    return v;
}
__device__ __forceinline__ uint4 ldg_consume_u4(const unsigned* p, u64 pol) {
    uint4 v;
    asm volatile("ld.global.L2::cache_hint.v4.u32 {%0,%1,%2,%3}, [%4], %5;"
                 : "=r"(v.x), "=r"(v.y), "=r"(v.z), "=r"(v.w) : "l"(p), "l"(pol));
    return v;
}
__device__ __forceinline__ void stg_keep_u4(unsigned* p, uint4 v, u64 pol) {
    asm volatile("st.global.L2::cache_hint.v4.u32 [%0], {%1,%2,%3,%4}, %5;"
                 :: "l"(p), "r"(v.x), "r"(v.y), "r"(v.z), "r"(v.w), "l"(pol)
                 : "memory");
}

__device__ __forceinline__ unsigned f2_to_h2(u64 v) {
    float lo, hi; upk2(v, lo, hi);
    __half2 h = __floats2half2_rn(lo, hi);
    return *reinterpret_cast<unsigned*>(&h);
}
__device__ __forceinline__ u64 h2_to_f2(unsigned u) {
    __half2 h = *reinterpret_cast<__half2*>(&u);
    float2 f = __half22float2(h);
    return pk2(f.x, f.y);
}

// Complex 4x4 gate on a quad; weights packed (wr,wi). Two-phase A/B form.
__device__ __forceinline__ void gate4(u64& v0, u64& v1, u64& v2, u64& v3,
                                      const u64* __restrict__ w)
{
    float r0,i0,r1,i1,r2,i2,r3,i3;
    upk2(v0,r0,i0); upk2(v1,r1,i1); upk2(v2,r2,i2); upk2(v3,r3,i3);

    u64 P0 = pk2(r0, r0), P1 = pk2(r1, r1), P2 = pk2(r2, r2), P3 = pk2(r3, r3);
    u64 A0 = fmul2(P0, w[0]);
    A0 = ffma2(P1, w[1], A0); A0 = ffma2(P2, w[2], A0); A0 = ffma2(P3, w[3], A0);
    u64 A1 = fmul2(P0, w[4]);
    A1 = ffma2(P1, w[5], A1); A1 = ffma2(P2, w[6], A1); A1 = ffma2(P3, w[7], A1);
    u64 A2 = fmul2(P0, w[8]);
    A2 = ffma2(P1, w[9], A2); A2 = ffma2(P2, w[10], A2); A2 = ffma2(P3, w[11], A2);
    u64 A3 = fmul2(P0, w[12]);
    A3 = ffma2(P1, w[13], A3); A3 = ffma2(P2, w[14], A3); A3 = ffma2(P3, w[15], A3);

    u64 Q0 = pk2(i0, i0), Q1 = pk2(i1, i1), Q2 = pk2(i2, i2), Q3 = pk2(i3, i3);
    {
        u64 B = fmul2(Q0, w[0]);
        B = ffma2(Q1, w[1], B); B = ffma2(Q2, w[2], B); B = ffma2(Q3, w[3], B);
        float bl, bh; upk2(B, bl, bh);
        v0 = fadd2(A0, pk2(negf(bh), bl));
    }
    {
        u64 B = fmul2(Q0, w[4]);
        B = ffma2(Q1, w[5], B); B = ffma2(Q2, w[6], B); B = ffma2(Q3, w[7], B);
        float bl, bh; upk2(B, bl, bh);
        v1 = fadd2(A1, pk2(negf(bh), bl));
    }
    {
        u64 B = fmul2(Q0, w[8]);
        B = ffma2(Q1, w[9], B); B = ffma2(Q2, w[10], B); B = ffma2(Q3, w[11], B);
        float bl, bh; upk2(B, bl, bh);
        v2 = fadd2(A2, pk2(negf(bh), bl));
    }
    {
        u64 B = fmul2(Q0, w[12]);
        B = ffma2(Q1, w[13], B); B = ffma2(Q2, w[14], B); B = ffma2(Q3, w[15], B);
        float bl, bh; upk2(B, bl, bh);
        v3 = fadd2(A3, pk2(negf(bh), bl));
    }
}

__device__ __forceinline__ unsigned expand4(unsigned t, int P0, int P1, int P2, int P3) {
    unsigned x = t;
    x = ((x & ~((1u << P0) - 1u)) << 1) | (x & ((1u << P0) - 1u));
    x = ((x & ~((1u << P1) - 1u)) << 1) | (x & ((1u << P1) - 1u));
    x = ((x & ~((1u << P2) - 1u)) << 1) | (x & ((1u << P2) - 1u));
    x = ((x & ~((1u << P3) - 1u)) << 1) | (x & ((1u << P3) - 1u));
    return x;
}

// Two fused gates on a 16-amp supergroup via smem round trip.
template <int P0, int P1, int P2, int P3>
__device__ __forceinline__ void apply_pair(float2* sm, unsigned tid,
                                           const float* __restrict__ gp0,
                                           const float* __restrict__ gp1)
{
    const unsigned x = expand4(tid, P0, P1, P2, P3);

    u64 p[16];
    #pragma unroll
    for (int i = 0; i < 16; ++i) {
        unsigned off = ((i & 1)        ? (1u << P0) : 0u)
                     | (((i >> 1) & 1) ? (1u << P1) : 0u)
                     | (((i >> 2) & 1) ? (1u << P2) : 0u)
                     | (((i >> 3) & 1) ? (1u << P3) : 0u);
        float2 v = sm[SWZ(x | off)];
        p[i] = pk2(v.x, v.y);
    }

    {   u64 w[16];
        #pragma unroll
        for (int k = 0; k < 16; ++k)
            w[k] = pk2(__ldg(gp0 + k), __ldg(gp0 + 16 + k));
        gate4(p[0],  p[1],  p[4],  p[5],  w);
        gate4(p[2],  p[3],  p[6],  p[7],  w);
        gate4(p[8],  p[9],  p[12], p[13], w);
        gate4(p[10], p[11], p[14], p[15], w);
    }
    {   u64 w[16];
        #pragma unroll
        for (int k = 0; k < 16; ++k)
            w[k] = pk2(__ldg(gp1 + k), __ldg(gp1 + 16 + k));
        gate4(p[0], p[2], p[8],  p[10], w);
        gate4(p[1], p[3], p[9],  p[11], w);
        gate4(p[4], p[6], p[12], p[14], w);
        gate4(p[5], p[7], p[13], p[15], w);
    }

    #pragma unroll
    for (int i = 0; i < 16; ++i) {
        unsigned off = ((i & 1)        ? (1u << P0) : 0u)
                     | (((i >> 1) & 1) ? (1u << P1) : 0u)
                     | (((i >> 2) & 1) ? (1u << P2) : 0u)
                     | (((i >> 3) & 1) ? (1u << P3) : 0u);
        float lo, hi; upk2(p[i], lo, hi);
        sm[SWZ(x | off)] = make_float2(lo, hi);
    }
}

// ---- pass0 tile: gates 0..4 on tile = amp bits {0..5,7..11}; b -> {6,12..23} ----
__device__ __forceinline__ void pass0_tile(float2* sm, unsigned b, unsigned t,
                                           const float* __restrict__ in,
                                           const float* __restrict__ gates)
{
    const unsigned hi = ((b & 1u) << 6) | ((b >> 1) << 12);

    // ph1: fused fp32 LDG (stream) + gate4 (amp 4,11 -> tile 4,10) + STS.
    {
        const u64 polF = mkpol_evict_first();
        u64 w[16];
        #pragma unroll
        for (int k = 0; k < 16; ++k)
            w[k] = pk2(__ldg(gates + 4 * 32 + k), __ldg(gates + 4 * 32 + 16 + k));

        const unsigned B = ((t & 3u) << 2) | ((t >> 2) << 5);
        u64 p[16];
        #pragma unroll
        for (int q = 0; q < 4; ++q) {
            unsigned a0 = B | ((q & 1u) << 4) | ((unsigned)(q >> 1) << 10);
            unsigned g = hi | (a0 & 63u) | ((a0 >> 6) << 7);
            float4 r4 = ldg_stream(in + g, polF);
            float4 m4 = ldg_stream(in + NSTATE + g, polF);
            p[q * 4 + 0] = pk2(r4.x, m4.x);
            p[q * 4 + 1] = pk2(r4.y, m4.y);
            p[q * 4 + 2] = pk2(r4.z, m4.z);
            p[q * 4 + 3] = pk2(r4.w, m4.w);
        }
        #pragma unroll
        for (int f = 0; f < 4; ++f)
            gate4(p[f], p[f + 4], p[f + 8], p[f + 12], w);
        #pragma unroll
        for (int i = 0; i < 16; ++i) {
            unsigned a = B | (unsigned)(i & 3)
                       | (((unsigned)(i >> 2) & 1u) << 4)
                       | (((unsigned)(i >> 3) & 1u) << 10);
            float lo, hic; upk2(p[i], lo, hic);
            sm[SWZ(a)] = make_float2(lo, hic);
        }
    }
    __syncthreads();

    // ph2: gates 2,3 -> tile <2,3,8,9>, smem round trip.
    apply_pair<2, 3, 8, 9>(sm, t, gates + 2 * 32, gates + 3 * 32);
    __syncthreads();

    // ph3: gates 0,1 -> tile <0,1,6,7>, direct fp16 STG pinned in L2.
    {
        const u64 polL = mkpol_evict_last();
        const unsigned x = expand4(t, 0, 1, 6, 7);
        u64 p[16];
        #pragma unroll
        for (int i = 0; i < 16; ++i) {
            unsigned off = (i & 3u) | (((i >> 2) & 1) << 6) | (((i >> 3) & 1) << 7);
            float2 v = sm[SWZ(x | off)];
            p[i] = pk2(v.x, v.y);
        }
        {   u64 w[16];
            #pragma unroll
            for (int k = 0; k < 16; ++k)
                w[k] = pk2(__ldg(gates + k), __ldg(gates + 16 + k));
            gate4(p[0],  p[1],  p[4],  p[5],  w);
            gate4(p[2],  p[3],  p[6],  p[7],  w);
            gate4(p[8],  p[9],  p[12], p[13], w);
            gate4(p[10], p[11], p[14], p[15], w);
        }
        {   u64 w[16];
            #pragma unroll
            for (int k = 0; k < 16; ++k)
                w[k] = pk2(__ldg(gates + 32 + k), __ldg(gates + 48 + k));
            gate4(p[0], p[2], p[8],  p[10], w);
            gate4(p[1], p[3], p[9],  p[11], w);
            gate4(p[4], p[6], p[12], p[14], w);
            gate4(p[5], p[7], p[13], p[15], w);
        }
        #pragma unroll
        for (int h = 0; h < 4; ++h) {
            unsigned bi = h << 2;
            unsigned a = x | ((h & 1u) << 6) | ((unsigned)(h >> 1) << 7);
            unsigned g = hi | (a & 63u) | ((a >> 6) << 7);
            uint4 u;
            u.x = f2_to_h2(p[bi + 0]);
            u.y = f2_to_h2(p[bi + 1]);
            u.z = f2_to_h2(p[bi + 2]);
            u.w = f2_to_h2(p[bi + 3]);
            stg_keep_u4(g_mid + g, u, polL);
        }
    }
}

// ---- pass1 tile: gates 5..7 on tile = amp bits {0..7,12..14}; b -> {8..11,15..23} ----
__device__ __forceinline__ void pass1_tile(float2* sm, unsigned b, unsigned t,
                                           float* __restrict__ st,
                                           const float* __restrict__ gates)
{
    const unsigned hi = ((b & 15u) << 8) | ((b >> 4) << 15);

    // ph1: fused fp16 LDG (consume) + gate7 (amp 7,14 -> tile 7,10) + STS.
    {
        const u64 polF = mkpol_evict_first();
        u64 w[16];
        #pragma unroll
        for (int k = 0; k < 16; ++k)
            w[k] = pk2(__ldg(gates + 7 * 32 + k), __ldg(gates + 7 * 32 + 16 + k));

        const unsigned B = ((t & 31u) << 2) | (((t >> 5) & 3u) << 8);
        u64 p[16];
        #pragma unroll
        for (int q = 0; q < 4; ++q) {
            unsigned a0 = B | ((q & 1u) << 7) | ((unsigned)(q >> 1) << 10);
            unsigned g = hi | (a0 & 255u) | ((a0 >> 8) << 12);
            uint4 u = ldg_consume_u4(g_mid + g, polF);
            p[q * 4 + 0] = h2_to_f2(u.x);
            p[q * 4 + 1] = h2_to_f2(u.y);
            p[q * 4 + 2] = h2_to_f2(u.z);
            p[q * 4 + 3] = h2_to_f2(u.w);
        }
        #pragma unroll
        for (int f = 0; f < 4; ++f)
            gate4(p[f], p[f + 4], p[f + 8], p[f + 12], w);
        #pragma unroll
        for (int i = 0; i < 16; ++i) {
            unsigned a = B | (unsigned)(i & 3)
                       | (((unsigned)(i >> 2) & 1u) << 7)
                       | (((unsigned)(i >> 3) & 1u) << 10);
            float lo, hic; upk2(p[i], lo, hic);
            sm[SWZ(a)] = make_float2(lo, hic);
        }
    }
    __syncthreads();

    // ph2: gates 5,6 -> tile <5,6,8,9>, LDS + direct STG.32 (128B-coalesced).
    {
        const unsigned x = expand4(t, 5, 6, 8, 9);
        u64 p[16];
        #pragma unroll
        for (int i = 0; i < 16; ++i) {
            unsigned off = ((i & 1u) << 5) | (((i >> 1) & 1u) << 6)
                         | (((i >> 2) & 1u) << 8) | (((i >> 3) & 1u) << 9);
            float2 v = sm[SWZ(x | off)];
            p[i] = pk2(v.x, v.y);
        }
        {   u64 w[16];
            #pragma unroll
            for (int k = 0; k < 16; ++k)
                w[k] = pk2(__ldg(gates + 5 * 32 + k), __ldg(gates + 5 * 32 + 16 + k));
            gate4(p[0],  p[1],  p[4],  p[5],  w);
            gate4(p[2],  p[3],  p[6],  p[7],  w);
            gate4(p[8],  p[9],  p[12], p[13], w);
            gate4(p[10], p[11], p[14], p[15], w);
        }
        {   u64 w[16];
            #pragma unroll
            for (int k = 0; k < 16; ++k)
                w[k] = pk2(__ldg(gates + 6 * 32 + k), __ldg(gates + 6 * 32 + 16 + k));
            gate4(p[0], p[2], p[8],  p[10], w);
            gate4(p[1], p[3], p[9],  p[11], w);
            gate4(p[4], p[6], p[12], p[14], w);
            gate4(p[5], p[7], p[13], p[15], w);
        }
        #pragma unroll
        for (int i = 0; i < 16; ++i) {
            unsigned off = ((i & 1u) << 5) | (((i >> 1) & 1u) << 6)
                         | (((i >> 2) & 1u) << 8) | (((i >> 3) & 1u) << 9);
            unsigned a = x | off;
            unsigned g = hi | (a & 255u) | ((a >> 8) << 12);
            float lo, hic; upk2(p[i], lo, hic);
            st[g] = lo;
            st[NSTATE + g] = hic;
        }
    }
}

// ---- reset: zero the work counter and chunk counters each launch ----
__global__ void qsim_reset()
{
    if (threadIdx.x == 0) g_next = 0;
    if (threadIdx.x < 512) g_done[threadIdx.x] = 0;
}

// ---- fused persistent kernel ----
__global__ __launch_bounds__(128, 5)
void qsim_fused(const float* __restrict__ in, float* __restrict__ out,
                const float* __restrict__ gates)
{
    __shared__ float2 sm[2048];
    __shared__ int s_item;
    const unsigned t = threadIdx.x;

    for (;;) {
        if (t == 0) s_item = atomicAdd(&g_next, 1);
        __syncthreads();            // broadcasts item; also fences smem reuse
        const int item = s_item;
        if (item >= 16384) return;

        if (item < 8192) {
            pass0_tile(sm, (unsigned)item, t, in, gates);
            __threadfence();        // make fp16 mid stores visible GPU-wide
            __syncthreads();        // all threads' stores+fences done
            if (t == 0) atomicAdd(&g_done[item >> 4], 1);
        } else {
            const unsigned j = (unsigned)(item - 8192);
            if (t == 0) {
                const int* cp = &g_done[j >> 4];
                int v;
                do {
                    asm volatile("ld.global.acquire.gpu.s32 %0, [%1];"
                                 : "=r"(v) : "l"(cp));
                    if (v < 16) __nanosleep(128);
                } while (v < 16);
            }
            __syncthreads();        // all threads see the acquire
            pass1_tile(sm, j, t, out, gates);
        }
    }
}

extern "C" void kernel_launch(void* const* d_in, const int* in_sizes, int n_in,
                              void* d_out, int out_size)
{
    const float* state = (const float*)d_in[0];   // 2 * 2^24 floats (re, im planes)
    const float* gates = (const float*)d_in[1];   // 8 * 2 * 4 * 4 floats
    float* out = (float*)d_out;

    qsim_reset<<<1, 512>>>();
    qsim_fused<<<740, 128>>>(state, out, gates);  // 148 SMs x 5 CTAs, persistent
}